// round 17
// baseline (speedup 1.0000x reference)
#include <cuda_runtime.h>
#include <cuda_bf16.h>

#define L_SEQ  2048
#define NB     4
#define NHEAD  16
#define HDIM   64
#define DMODEL 1024

// ---------------------------------------------------------------------------
// Device-global scratch (tf32-rounded fp32; Q pre-scaled by 0.125)
// g_q/g_k: [bh][l][64].  g_vt: V transposed [bh][d][L]
// ---------------------------------------------------------------------------
__device__ float g_q[(size_t)NB * NHEAD * L_SEQ * HDIM];
__device__ float g_k[(size_t)NB * NHEAD * L_SEQ * HDIM];
__device__ float g_vt[(size_t)NB * NHEAD * HDIM * L_SEQ];

// ---------------------------------------------------------------------------
// Helpers
// ---------------------------------------------------------------------------
__device__ __forceinline__ unsigned cvt_tf32(float f) {
    unsigned u;
    asm("cvt.rna.tf32.f32 %0, %1;" : "=r"(u) : "f"(f));
    return u;
}
// tf32 m16n8k8
__device__ __forceinline__ void mma1688(float c[4], const unsigned a[4],
                                        unsigned b0, unsigned b1) {
    asm volatile(
        "mma.sync.aligned.m16n8k8.row.col.f32.tf32.tf32.f32 "
        "{%0,%1,%2,%3}, {%4,%5,%6,%7}, {%8,%9}, {%0,%1,%2,%3};"
        : "+f"(c[0]), "+f"(c[1]), "+f"(c[2]), "+f"(c[3])
        : "r"(a[0]), "r"(a[1]), "r"(a[2]), "r"(a[3]), "r"(b0), "r"(b1));
}

// ---------------------------------------------------------------------------
// QKV GEMM via tf32 mma.sync with REGISTER PREFETCH: while mma consumes
// chunk k from smem, chunk k+1's global loads are in flight to registers.
// CTA: 128 thr (4 warps), tile 64m x 64n, k-chunks of 64. grid (128,16,3).
// Q (z=0): scaled by 0.125, tf32 -> g_q. K (z=1): tf32 -> g_k.
// V (z=2): tf32, TRANSPOSED via smem staging -> g_vt[bh][d][L] (coalesced).
// ---------------------------------------------------------------------------
__global__ __launch_bounds__(128) void qkv_kernel(
    const float* __restrict__ x,
    const float* __restrict__ wq, const float* __restrict__ bq,
    const float* __restrict__ wk, const float* __restrict__ bk,
    const float* __restrict__ wv, const float* __restrict__ bv)
{
    __shared__ __align__(16) float sx[64 * 68];
    __shared__ __align__(16) float sw[64 * 68];

    const int z    = blockIdx.z;
    const int tid  = threadIdx.x;
    const int warp = tid >> 5;
    const int l    = tid & 31;
    const int m0   = blockIdx.x * 64;
    const int h    = blockIdx.y;
    const int n0   = h * 64;

    const float* w;
    const float* bias;
    if (z == 0)      { w = wq; bias = bq; }
    else if (z == 1) { w = wk; bias = bk; }
    else             { w = wv; bias = bv; }

    float acc[8][4] = {};
    const unsigned* sxu = (const unsigned*)sx;
    const unsigned* swu = (const unsigned*)sw;

    // per-thread load coordinates (fixed across chunks)
    const int lrow = tid >> 4;            // 0..7  (row base; +8i below... no:)
    // each thread handles 8 granules: rows g>>4 for g = tid + 128i
    float4 px[8], pw[8];

    // prologue: prefetch chunk 0
    #pragma unroll
    for (int i = 0; i < 8; i++) {
        int g = tid + i * 128;
        int row = g >> 4, c4 = g & 15;
        px[i] = *(const float4*)&x[(size_t)(m0 + row) * DMODEL + c4 * 4];
        pw[i] = *(const float4*)&w[(size_t)(n0 + row) * DMODEL + c4 * 4];
    }
    (void)lrow;

    for (int k0 = 0; k0 < DMODEL; k0 += 64) {
        // store prefetched chunk to smem (cvt at store — numerics unchanged)
        #pragma unroll
        for (int i = 0; i < 8; i++) {
            int g = tid + i * 128;
            int row = g >> 4, c4 = g & 15;
            unsigned* dx = (unsigned*)&sx[row * 68 + c4 * 4];
            unsigned* dw = (unsigned*)&sw[row * 68 + c4 * 4];
            dx[0] = cvt_tf32(px[i].x); dx[1] = cvt_tf32(px[i].y);
            dx[2] = cvt_tf32(px[i].z); dx[3] = cvt_tf32(px[i].w);
            dw[0] = cvt_tf32(pw[i].x); dw[1] = cvt_tf32(pw[i].y);
            dw[2] = cvt_tf32(pw[i].z); dw[3] = cvt_tf32(pw[i].w);
        }
        __syncthreads();

        // prefetch next chunk (LDGs overlap the mma below)
        if (k0 + 64 < DMODEL) {
            #pragma unroll
            for (int i = 0; i < 8; i++) {
                int g = tid + i * 128;
                int row = g >> 4, c4 = g & 15;
                px[i] = *(const float4*)&x[(size_t)(m0 + row) * DMODEL + k0 + 64 + c4 * 4];
                pw[i] = *(const float4*)&w[(size_t)(n0 + row) * DMODEL + k0 + 64 + c4 * 4];
            }
        }

        const int ar = warp * 16 + (l >> 2);
        const int tc = l & 3;
        #pragma unroll
        for (int ks = 0; ks < 8; ks++) {
            const int ac = ks * 8 + tc;
            unsigned a[4];
            a[0] = sxu[ar * 68 + ac];
            a[1] = sxu[(ar + 8) * 68 + ac];
            a[2] = sxu[ar * 68 + ac + 4];
            a[3] = sxu[(ar + 8) * 68 + ac + 4];
            #pragma unroll
            for (int nt = 0; nt < 8; nt++) {
                const int br = nt * 8 + (l >> 2);
                unsigned b0 = swu[br * 68 + ac];
                unsigned b1 = swu[br * 68 + ac + 4];
                mma1688(acc[nt], a, b0, b1);
            }
        }
        __syncthreads();   // smem consumed; next store may proceed
    }

    // epilogue
    const int lm = warp * 16 + (l >> 2);        // local m (0..63), rows lm, lm+8
    const int c0 = (l & 3) * 2;
    const int bi = m0 >> 11;
    const int lg = (m0 + lm) & (L_SEQ - 1);     // l within batch
    const size_t bhbase = (size_t)(bi * NHEAD + h) * L_SEQ;

    if (z == 2) {
        // stage transposed into sx as [d][m] (stride 68), then coalesced out.
        #pragma unroll
        for (int nt = 0; nt < 8; nt++) {
            const int d = nt * 8 + c0;
            float2 b2 = *(const float2*)&bias[n0 + d];
            sx[d * 68 + lm]           = __uint_as_float(cvt_tf32(acc[nt][0] + b2.x));
            sx[(d + 1) * 68 + lm]     = __uint_as_float(cvt_tf32(acc[nt][1] + b2.y));
            sx[d * 68 + lm + 8]       = __uint_as_float(cvt_tf32(acc[nt][2] + b2.x));
            sx[(d + 1) * 68 + lm + 8] = __uint_as_float(cvt_tf32(acc[nt][3] + b2.y));
        }
        __syncthreads();
        const size_t vbase = (size_t)(bi * NHEAD + h) * HDIM * L_SEQ;
        const int l0 = m0 & (L_SEQ - 1);
        #pragma unroll
        for (int i = 0; i < 8; i++) {
            int g = tid + i * 128;
            int row = g >> 4, c4 = g & 15;
            *(float4*)&g_vt[vbase + (size_t)row * L_SEQ + l0 + c4 * 4] =
                *(const float4*)&sx[row * 68 + c4 * 4];
        }
    } else {
        float* dst = (z == 0) ? g_q : g_k;
        const float sc = (z == 0) ? 0.125f : 1.0f;
        #pragma unroll
        for (int nt = 0; nt < 8; nt++) {
            const int d = nt * 8 + c0;
            float2 b2 = *(const float2*)&bias[n0 + d];
            float v0 = (acc[nt][0] + b2.x) * sc, v1 = (acc[nt][1] + b2.y) * sc;
            float v2 = (acc[nt][2] + b2.x) * sc, v3 = (acc[nt][3] + b2.y) * sc;
            *(float2*)&dst[(bhbase + lg) * HDIM + d] =
                make_float2(__uint_as_float(cvt_tf32(v0)), __uint_as_float(cvt_tf32(v1)));
            *(float2*)&dst[(bhbase + lg + 8) * HDIM + d] =
                make_float2(__uint_as_float(cvt_tf32(v2)), __uint_as_float(cvt_tf32(v3)));
        }
    }
}

// ---------------------------------------------------------------------------
// Flash attention, all-tf32 mma. 4 warps, each m32 x n64 (two m16 tiles mt):
// every B-fragment LDS (QK and PV) feeds TWO mma -> smem bytes cut ~36%.
// CTA: 128 thr, 128 q-rows, K-tiles of 64. grid (16, 64).
// ---------------------------------------------------------------------------
__global__ __launch_bounds__(128, 2) void attn_kernel(
    const float* __restrict__ mask, float* __restrict__ out)
{
    extern __shared__ __align__(16) float smem[];
    float* sQ = smem;                 // [128][72] tf32
    float* sK = smem + 128 * 72;      // [64][72]  tf32
    float* sV = smem + 192 * 72;      // [64][72]  V^T: [d][kc], tf32

    const int tid  = threadIdx.x;
    const int warp = tid >> 5;            // 0..3
    const int l    = tid & 31;
    const int rq   = l >> 2;
    const int tcol = (l & 3) * 2;
    const int rt   = blockIdx.x;          // q tile of 128
    const int bh   = blockIdx.y;
    const int bi   = bh >> 4;
    const int h    = bh & 15;

    const size_t bhoff = (size_t)bh * L_SEQ;
    const size_t vtoff = (size_t)bh * HDIM * L_SEQ;

    // load Q tile: 2048 float4 / 128 thr = 16 iters
    #pragma unroll
    for (int i = 0; i < 16; i++) {
        int g = tid + i * 128;
        int row = g >> 4, c4 = g & 15;
        *(float4*)&sQ[row * 72 + c4 * 4] =
            *(const float4*)&g_q[(bhoff + rt * 128 + row) * HDIM + c4 * 4];
    }

    const int qr = warp * 32 + rq;        // warp's rows: qr, +8, +16, +24

    float mi[2][2], li[2][2];
    #pragma unroll
    for (int mt = 0; mt < 2; mt++) {
        mi[mt][0] = -1e30f; mi[mt][1] = -1e30f;
        li[mt][0] = 0.0f;   li[mt][1] = 0.0f;
    }
    float oacc[2][8][4] = {};

    const float* Mbase = mask + ((size_t)bi * L_SEQ + rt * 128) * L_SEQ;

    for (int kt = 0; kt < L_SEQ / 64; kt++) {
        if (kt) __syncthreads();
        // K tile: 1024 float4 / 128 thr = 8 iters
        #pragma unroll
        for (int i = 0; i < 8; i++) {
            int g = tid + i * 128;
            int row = g >> 4, c4 = g & 15;
            *(float4*)&sK[row * 72 + c4 * 4] =
                *(const float4*)&g_k[(bhoff + kt * 64 + row) * HDIM + c4 * 4];
        }
        // V^T tile: 8 iters, coalesced
        #pragma unroll
        for (int i = 0; i < 8; i++) {
            int g = tid + i * 128;
            int row = g >> 4, c4 = g & 15;
            *(float4*)&sV[row * 72 + c4 * 4] =
                *(const float4*)&g_vt[vtoff + (size_t)row * L_SEQ + kt * 64 + c4 * 4];
        }
        __syncthreads();

        // ---- S = Q K^T (tf32, Q pre-scaled); B shared across both m-tiles ----
        float sacc[2][8][4] = {};
        #pragma unroll
        for (int ks = 0; ks < 8; ks++) {
            const int ac = ks * 8 + tcol;
            float2 q00 = *(const float2*)&sQ[qr * 72 + ac];
            float2 q01 = *(const float2*)&sQ[(qr + 8) * 72 + ac];
            float2 q10 = *(const float2*)&sQ[(qr + 16) * 72 + ac];
            float2 q11 = *(const float2*)&sQ[(qr + 24) * 72 + ac];
            unsigned a0[4] = { __float_as_uint(q00.x), __float_as_uint(q01.x),
                               __float_as_uint(q00.y), __float_as_uint(q01.y) };
            unsigned a1[4] = { __float_as_uint(q10.x), __float_as_uint(q11.x),
                               __float_as_uint(q10.y), __float_as_uint(q11.y) };
            #pragma unroll
            for (int nt = 0; nt < 8; nt++) {
                float2 b = *(const float2*)&sK[(nt * 8 + rq) * 72 + ac];
                unsigned b0 = __float_as_uint(b.x), b1 = __float_as_uint(b.y);
                mma1688(sacc[0][nt], a0, b0, b1);
                mma1688(sacc[1][nt], a1, b0, b1);
            }
        }

        // ---- mask add + online softmax per m-tile ----
        #pragma unroll
        for (int mt = 0; mt < 2; mt++) {
            const float* M0 = Mbase + (size_t)(qr + mt * 16) * L_SEQ + kt * 64;
            const float* M1 = M0 + 8 * L_SEQ;
            #pragma unroll
            for (int nt = 0; nt < 8; nt++) {
                float2 mk0 = *(const float2*)&M0[nt * 8 + tcol];
                float2 mk1 = *(const float2*)&M1[nt * 8 + tcol];
                sacc[mt][nt][0] += mk0.x; sacc[mt][nt][1] += mk0.y;
                sacc[mt][nt][2] += mk1.x; sacc[mt][nt][3] += mk1.y;
            }

            float mx0 = -1e30f, mx1 = -1e30f;
            #pragma unroll
            for (int nt = 0; nt < 8; nt++) {
                mx0 = fmaxf(mx0, fmaxf(sacc[mt][nt][0], sacc[mt][nt][1]));
                mx1 = fmaxf(mx1, fmaxf(sacc[mt][nt][2], sacc[mt][nt][3]));
            }
            mx0 = fmaxf(mx0, __shfl_xor_sync(0xffffffffu, mx0, 1));
            mx0 = fmaxf(mx0, __shfl_xor_sync(0xffffffffu, mx0, 2));
            mx1 = fmaxf(mx1, __shfl_xor_sync(0xffffffffu, mx1, 1));
            mx1 = fmaxf(mx1, __shfl_xor_sync(0xffffffffu, mx1, 2));
            float mn0 = fmaxf(mi[mt][0], mx0), mn1 = fmaxf(mi[mt][1], mx1);
            float al0 = __expf(mi[mt][0] - mn0), al1 = __expf(mi[mt][1] - mn1);
            mi[mt][0] = mn0; mi[mt][1] = mn1;
            float sum0 = 0.0f, sum1 = 0.0f;
            #pragma unroll
            for (int nt = 0; nt < 8; nt++) {
                sacc[mt][nt][0] = __expf(sacc[mt][nt][0] - mn0);
                sacc[mt][nt][1] = __expf(sacc[mt][nt][1] - mn0);
                sacc[mt][nt][2] = __expf(sacc[mt][nt][2] - mn1);
                sacc[mt][nt][3] = __expf(sacc[mt][nt][3] - mn1);
                sum0 += sacc[mt][nt][0] + sacc[mt][nt][1];
                sum1 += sacc[mt][nt][2] + sacc[mt][nt][3];
            }
            sum0 += __shfl_xor_sync(0xffffffffu, sum0, 1);
            sum0 += __shfl_xor_sync(0xffffffffu, sum0, 2);
            sum1 += __shfl_xor_sync(0xffffffffu, sum1, 1);
            sum1 += __shfl_xor_sync(0xffffffffu, sum1, 2);
            li[mt][0] = li[mt][0] * al0 + sum0;
            li[mt][1] = li[mt][1] * al1 + sum1;
            #pragma unroll
            for (int nt = 0; nt < 8; nt++) {
                oacc[mt][nt][0] *= al0; oacc[mt][nt][1] *= al0;
                oacc[mt][nt][2] *= al1; oacc[mt][nt][3] *= al1;
            }
        }

        // ---- O += P V (tf32; S-frag IS the A-frag; B shared across m-tiles) ----
        #pragma unroll
        for (int kk = 0; kk < 8; kk++) {
            unsigned a0[4] = { cvt_tf32(sacc[0][kk][0]), cvt_tf32(sacc[0][kk][2]),
                               cvt_tf32(sacc[0][kk][1]), cvt_tf32(sacc[0][kk][3]) };
            unsigned a1[4] = { cvt_tf32(sacc[1][kk][0]), cvt_tf32(sacc[1][kk][2]),
                               cvt_tf32(sacc[1][kk][1]), cvt_tf32(sacc[1][kk][3]) };
            const int bc = kk * 8 + tcol;
            #pragma unroll
            for (int nt = 0; nt < 8; nt++) {
                float2 b = *(const float2*)&sV[(nt * 8 + rq) * 72 + bc];
                unsigned b0 = __float_as_uint(b.x), b1 = __float_as_uint(b.y);
                mma1688(oacc[0][nt], a0, b0, b1);
                mma1688(oacc[1][nt], a1, b0, b1);
            }
        }
    }

    // ---- normalize + write out[b, l, h*64 + d] ----
    #pragma unroll
    for (int mt = 0; mt < 2; mt++) {
        const float inv0 = 1.0f / li[mt][0], inv1 = 1.0f / li[mt][1];
        const int gr0 = rt * 128 + qr + mt * 16;
        #pragma unroll
        for (int nt = 0; nt < 8; nt++) {
            const int d = nt * 8 + tcol;
            *(float2*)&out[((size_t)bi * L_SEQ + gr0) * DMODEL + h * HDIM + d] =
                make_float2(oacc[mt][nt][0] * inv0, oacc[mt][nt][1] * inv0);
            *(float2*)&out[((size_t)bi * L_SEQ + gr0 + 8) * DMODEL + h * HDIM + d] =
                make_float2(oacc[mt][nt][2] * inv1, oacc[mt][nt][3] * inv1);
        }
    }
}

// ---------------------------------------------------------------------------
extern "C" void kernel_launch(void* const* d_in, const int* in_sizes, int n_in,
                              void* d_out, int out_size)
{
    const float* x    = (const float*)d_in[0];
    const float* mask = (const float*)d_in[1];
    const float* wq   = (const float*)d_in[2];
    const float* bq   = (const float*)d_in[3];
    const float* wk   = (const float*)d_in[4];
    const float* bk   = (const float*)d_in[5];
    const float* wv   = (const float*)d_in[6];
    const float* bv   = (const float*)d_in[7];
    float* out = (float*)d_out;

    dim3 gq(128, 16, 3);
    qkv_kernel<<<gq, 128>>>(x, wq, bq, wk, bk, wv, bv);

    const int smem_attn = 256 * 72 * (int)sizeof(float);   // 73728
    cudaFuncSetAttribute(attn_kernel,
                         cudaFuncAttributeMaxDynamicSharedMemorySize, smem_attn);
    dim3 ga(16, 64);
    attn_kernel<<<ga, 128, smem_attn>>>(mask, out);
}